// round 1
// baseline (speedup 1.0000x reference)
#include <cuda_runtime.h>
#include <math.h>

#define DIMV    2048
#define SEQ     2048
#define BATCH   2
#define HEADS   16
#define DHEAD   128
#define MROWS   (BATCH*SEQ)   // 4096
#define EPSV    1e-5f

// Scratch (device globals: no allocations allowed)
__device__ float g_q[(size_t)MROWS * DIMV];
__device__ float g_k[(size_t)MROWS * DIMV];
__device__ float g_v[(size_t)MROWS * DIMV];
__device__ float g_attn[(size_t)MROWS * DIMV];

// ---------------------------------------------------------------------------
// C[M,N] = A[M,K] @ W[N,K]^T + bias[N]   (fp32, 128x128x8 tiles, 8x8/thread)
// ---------------------------------------------------------------------------
__global__ __launch_bounds__(256, 2)
void sgemm_bias_kernel(const float* __restrict__ A, const float* __restrict__ W,
                       const float* __restrict__ bias, float* __restrict__ C,
                       int M, int N, int K)
{
    __shared__ float As[8][128];
    __shared__ float Bs[8][128];
    const int tid  = threadIdx.x;
    const int tx   = tid & 15;
    const int ty   = tid >> 4;
    const int m0   = blockIdx.y * 128;
    const int n0   = blockIdx.x * 128;
    const int lrow = tid >> 1;          // 0..127
    const int lk   = (tid & 1) * 4;     // 0 or 4

    const float* Ap = A + (size_t)(m0 + lrow) * K + lk;
    const float* Wp = W + (size_t)(n0 + lrow) * K + lk;

    float acc[8][8];
#pragma unroll
    for (int i = 0; i < 8; i++)
#pragma unroll
        for (int j = 0; j < 8; j++) acc[i][j] = 0.f;

    float4 av = *(const float4*)Ap;
    float4 wv = *(const float4*)Wp;

    for (int k0 = 0; k0 < K; k0 += 8) {
        As[lk+0][lrow] = av.x; As[lk+1][lrow] = av.y;
        As[lk+2][lrow] = av.z; As[lk+3][lrow] = av.w;
        Bs[lk+0][lrow] = wv.x; Bs[lk+1][lrow] = wv.y;
        Bs[lk+2][lrow] = wv.z; Bs[lk+3][lrow] = wv.w;
        __syncthreads();
        if (k0 + 8 < K) {   // prefetch next tile while computing this one
            av = *(const float4*)(Ap + k0 + 8);
            wv = *(const float4*)(Wp + k0 + 8);
        }
#pragma unroll
        for (int kk = 0; kk < 8; kk++) {
            float4 a0 = *(const float4*)&As[kk][ty*8];
            float4 a1 = *(const float4*)&As[kk][ty*8 + 4];
            float4 b0 = *(const float4*)&Bs[kk][tx*8];
            float4 b1 = *(const float4*)&Bs[kk][tx*8 + 4];
            float a[8] = {a0.x,a0.y,a0.z,a0.w,a1.x,a1.y,a1.z,a1.w};
            float b[8] = {b0.x,b0.y,b0.z,b0.w,b1.x,b1.y,b1.z,b1.w};
#pragma unroll
            for (int i = 0; i < 8; i++)
#pragma unroll
                for (int j = 0; j < 8; j++)
                    acc[i][j] = fmaf(a[i], b[j], acc[i][j]);
        }
        __syncthreads();
    }

    float bb[8];
#pragma unroll
    for (int j = 0; j < 8; j++) bb[j] = bias[n0 + tx*8 + j];
#pragma unroll
    for (int i = 0; i < 8; i++) {
        float* Cp = C + (size_t)(m0 + ty*8 + i) * N + n0 + tx*8;
        float4 c0 = make_float4(acc[i][0]+bb[0], acc[i][1]+bb[1],
                                acc[i][2]+bb[2], acc[i][3]+bb[3]);
        float4 c1 = make_float4(acc[i][4]+bb[4], acc[i][5]+bb[5],
                                acc[i][6]+bb[6], acc[i][7]+bb[7]);
        *(float4*)Cp       = c0;
        *(float4*)(Cp + 4) = c1;
    }
}

// ---------------------------------------------------------------------------
// Fused RMSNorm (over inner=2048) + interleaved RoPE + history-key scaling.
// In-place on g_q and g_k. One block per (b,s) row, 256 threads * 8 elems.
// ---------------------------------------------------------------------------
__global__ __launch_bounds__(256)
void normrope_kernel(float* __restrict__ q, float* __restrict__ k,
                     const float* __restrict__ rot,
                     const float* __restrict__ wq, const float* __restrict__ wk,
                     const float* __restrict__ hks, const int* __restrict__ oclp)
{
    const int r   = blockIdx.x;         // 0..4095
    const int s   = r & (SEQ - 1);
    const int tid = threadIdx.x;
    float* qrow = q + (size_t)r * DIMV;
    float* krow = k + (size_t)r * DIMV;
    const int base = tid * 8;

    float qa[8], ka[8];
    {
        float4 t0 = *(const float4*)(qrow + base);
        float4 t1 = *(const float4*)(qrow + base + 4);
        qa[0]=t0.x; qa[1]=t0.y; qa[2]=t0.z; qa[3]=t0.w;
        qa[4]=t1.x; qa[5]=t1.y; qa[6]=t1.z; qa[7]=t1.w;
        float4 u0 = *(const float4*)(krow + base);
        float4 u1 = *(const float4*)(krow + base + 4);
        ka[0]=u0.x; ka[1]=u0.y; ka[2]=u0.z; ka[3]=u0.w;
        ka[4]=u1.x; ka[5]=u1.y; ka[6]=u1.z; ka[7]=u1.w;
    }

    float sq = 0.f, sk = 0.f;
#pragma unroll
    for (int i = 0; i < 8; i++) { sq = fmaf(qa[i], qa[i], sq); sk = fmaf(ka[i], ka[i], sk); }

    __shared__ float2 red[256];
    red[tid] = make_float2(sq, sk);
    __syncthreads();
#pragma unroll
    for (int off = 128; off > 0; off >>= 1) {
        if (tid < off) {
            red[tid].x += red[tid + off].x;
            red[tid].y += red[tid + off].y;
        }
        __syncthreads();
    }
    const float rq = rsqrtf(red[0].x * (1.f / DIMV) + EPSV);
    const float rk = rsqrtf(red[0].y * (1.f / DIMV) + EPSV);

    const int  hist    = SEQ - oclp[0];
    const bool is_hist = (s < hist);
    const float* rrow  = rot + (size_t)s * (2 * DHEAD);

    float qo[8], ko[8];
#pragma unroll
    for (int t = 0; t < 4; t++) {
        const int p = (base >> 1) + t;       // global pair index
        const int h = p >> 6;                // head (64 pairs per head)
        const int i = p & 63;                // pair index within head
        const float c  = rrow[2*i];                  // freqs[:D][0::2]
        const float si = rrow[DHEAD + 2*i + 1];      // freqs[D:][1::2]
        const int n = base + 2*t;
        float q1 = qa[2*t]     * rq * wq[n];
        float q2 = qa[2*t + 1] * rq * wq[n + 1];
        qo[2*t]     = q1*c - q2*si;
        qo[2*t + 1] = q1*si + q2*c;
        float k1 = ka[2*t]     * rk * wk[n];
        float k2 = ka[2*t + 1] * rk * wk[n + 1];
        float ke  = k1*c - k2*si;
        float kod = k1*si + k2*c;
        if (is_hist) {
            const float sc = 1.f + 9.f / (1.f + __expf(-hks[h]));
            ke *= sc; kod *= sc;
        }
        ko[2*t] = ke; ko[2*t + 1] = kod;
    }
    *(float4*)(qrow + base)     = make_float4(qo[0], qo[1], qo[2], qo[3]);
    *(float4*)(qrow + base + 4) = make_float4(qo[4], qo[5], qo[6], qo[7]);
    *(float4*)(krow + base)     = make_float4(ko[0], ko[1], ko[2], ko[3]);
    *(float4*)(krow + base + 4) = make_float4(ko[4], ko[5], ko[6], ko[7]);
}

// ---------------------------------------------------------------------------
// Flash attention (non-causal), fp32. Q/K/V in [b, s, h*128+d] layout.
// One block per (bh, 64-row q-tile). 256 threads, 80 KB dynamic smem.
// ---------------------------------------------------------------------------
#define BQ  64
#define BKV 64
#define ATT_SMEM ((128*64*2 + 64*64) * sizeof(float))   // Qs + KVs + Ps = 80 KB

__global__ __launch_bounds__(256, 2)
void flashattn_kernel(const float* __restrict__ Q, const float* __restrict__ K,
                      const float* __restrict__ V, float* __restrict__ O)
{
    extern __shared__ float smf[];
    float* Qs  = smf;               // [d][m]  : d*64 + m   (transposed)
    float* KVs = smf + 128*64;      // K: [d][n] d*64+n ; V: [kk][dd] kk*128+dd
    float* Ps  = smf + 2*128*64;    // [m][n]  : m*64 + n

    const int tid = threadIdx.x;
    const int tx  = tid & 15;
    const int ty  = tid >> 4;
    const int bh  = blockIdx.y;     // 0..31
    const int b   = bh >> 4;
    const int h   = bh & 15;
    const int q0  = blockIdx.x * BQ;

    const float* Qb = Q + ((size_t)b * SEQ) * DIMV + (size_t)h * DHEAD;
    const float* Kb = K + ((size_t)b * SEQ) * DIMV + (size_t)h * DHEAD;
    const float* Vb = V + ((size_t)b * SEQ) * DIMV + (size_t)h * DHEAD;

    const int lrow  = tid >> 2;        // 0..63
    const int dpart = (tid & 3) * 32;  // 0,32,64,96

    // Load Q tile, transposed Qs[d][m]
    {
        const float* src = Qb + (size_t)(q0 + lrow) * DIMV + dpart;
#pragma unroll
        for (int j = 0; j < 8; j++) {
            float4 v4 = *(const float4*)(src + j*4);
            const int d = dpart + j*4;
            Qs[(d+0)*64 + lrow] = v4.x; Qs[(d+1)*64 + lrow] = v4.y;
            Qs[(d+2)*64 + lrow] = v4.z; Qs[(d+3)*64 + lrow] = v4.w;
        }
    }

    float o[4][8];
#pragma unroll
    for (int i = 0; i < 4; i++)
#pragma unroll
        for (int j = 0; j < 8; j++) o[i][j] = 0.f;
    float mprev[4] = {-INFINITY, -INFINITY, -INFINITY, -INFINITY};
    float l[4]     = {0.f, 0.f, 0.f, 0.f};
    const float SCALE = 0.08838834764831845f;   // 1/sqrt(128)

    for (int kv0 = 0; kv0 < SEQ; kv0 += BKV) {
        __syncthreads();   // Qs ready (iter 0) / prev PV finished with KVs & Ps
        // Load K tile, transposed KVs[d][n]
        {
            const float* src = Kb + (size_t)(kv0 + lrow) * DIMV + dpart;
#pragma unroll
            for (int j = 0; j < 8; j++) {
                float4 v4 = *(const float4*)(src + j*4);
                const int d = dpart + j*4;
                KVs[(d+0)*64 + lrow] = v4.x; KVs[(d+1)*64 + lrow] = v4.y;
                KVs[(d+2)*64 + lrow] = v4.z; KVs[(d+3)*64 + lrow] = v4.w;
            }
        }
        __syncthreads();

        // S = Q @ K^T  (each thread: 4x4 of the 64x64 tile)
        float sacc[4][4];
#pragma unroll
        for (int i = 0; i < 4; i++)
#pragma unroll
            for (int j = 0; j < 4; j++) sacc[i][j] = 0.f;
#pragma unroll 8
        for (int d = 0; d < 128; d++) {
            float4 aq = *(const float4*)&Qs[d*64 + ty*4];
            float4 bk = *(const float4*)&KVs[d*64 + tx*4];
            float a[4] = {aq.x, aq.y, aq.z, aq.w};
            float bb[4] = {bk.x, bk.y, bk.z, bk.w};
#pragma unroll
            for (int i = 0; i < 4; i++)
#pragma unroll
                for (int j = 0; j < 4; j++)
                    sacc[i][j] = fmaf(a[i], bb[j], sacc[i][j]);
        }

        // Online softmax (rows owned by 16-lane half-warps)
#pragma unroll
        for (int i = 0; i < 4; i++) {
            float rmax = -INFINITY;
#pragma unroll
            for (int j = 0; j < 4; j++) { sacc[i][j] *= SCALE; rmax = fmaxf(rmax, sacc[i][j]); }
            rmax = fmaxf(rmax, __shfl_xor_sync(0xffffffffu, rmax, 8));
            rmax = fmaxf(rmax, __shfl_xor_sync(0xffffffffu, rmax, 4));
            rmax = fmaxf(rmax, __shfl_xor_sync(0xffffffffu, rmax, 2));
            rmax = fmaxf(rmax, __shfl_xor_sync(0xffffffffu, rmax, 1));
            const float mnew = fmaxf(mprev[i], rmax);
            float p0 = __expf(sacc[i][0] - mnew);
            float p1 = __expf(sacc[i][1] - mnew);
            float p2 = __expf(sacc[i][2] - mnew);
            float p3 = __expf(sacc[i][3] - mnew);
            float rsum = p0 + p1 + p2 + p3;
            rsum += __shfl_xor_sync(0xffffffffu, rsum, 8);
            rsum += __shfl_xor_sync(0xffffffffu, rsum, 4);
            rsum += __shfl_xor_sync(0xffffffffu, rsum, 2);
            rsum += __shfl_xor_sync(0xffffffffu, rsum, 1);
            const float alpha = __expf(mprev[i] - mnew);
            l[i] = l[i] * alpha + rsum;
            mprev[i] = mnew;
            *(float4*)&Ps[(ty*4 + i)*64 + tx*4] = make_float4(p0, p1, p2, p3);
#pragma unroll
            for (int j = 0; j < 8; j++) o[i][j] *= alpha;
        }
        __syncthreads();   // Ps complete; S-GEMM done reading KVs

        // Load V tile, row-major KVs[kk][dd]
        {
            const float* src = Vb + (size_t)(kv0 + lrow) * DIMV + dpart;
#pragma unroll
            for (int j = 0; j < 8; j++)
                *(float4*)&KVs[lrow*128 + dpart + j*4] = *(const float4*)(src + j*4);
        }
        __syncthreads();

        // O += P @ V
#pragma unroll 4
        for (int kk = 0; kk < BKV; kk++) {
            float a0 = Ps[(ty*4 + 0)*64 + kk];
            float a1 = Ps[(ty*4 + 1)*64 + kk];
            float a2 = Ps[(ty*4 + 2)*64 + kk];
            float a3 = Ps[(ty*4 + 3)*64 + kk];
            float4 b0 = *(const float4*)&KVs[kk*128 + tx*8];
            float4 b1 = *(const float4*)&KVs[kk*128 + tx*8 + 4];
            float bj[8] = {b0.x, b0.y, b0.z, b0.w, b1.x, b1.y, b1.z, b1.w};
#pragma unroll
            for (int j = 0; j < 8; j++) {
                o[0][j] = fmaf(a0, bj[j], o[0][j]);
                o[1][j] = fmaf(a1, bj[j], o[1][j]);
                o[2][j] = fmaf(a2, bj[j], o[2][j]);
                o[3][j] = fmaf(a3, bj[j], o[3][j]);
            }
        }
    }

    // Epilogue: normalize and write [b, s, h*128+d]
    float* Ob = O + ((size_t)b * SEQ) * DIMV + (size_t)h * DHEAD;
#pragma unroll
    for (int i = 0; i < 4; i++) {
        const float inv = 1.f / l[i];
        float* dst = Ob + (size_t)(q0 + ty*4 + i) * DIMV + tx*8;
        *(float4*)dst       = make_float4(o[i][0]*inv, o[i][1]*inv, o[i][2]*inv, o[i][3]*inv);
        *(float4*)(dst + 4) = make_float4(o[i][4]*inv, o[i][5]*inv, o[i][6]*inv, o[i][7]*inv);
    }
}

// ---------------------------------------------------------------------------
extern "C" void kernel_launch(void* const* d_in, const int* in_sizes, int n_in,
                              void* d_out, int out_size)
{
    const float* hs  = (const float*)d_in[0];
    const float* rot = (const float*)d_in[1];
    const float* Wq  = (const float*)d_in[2];
    const float* bq  = (const float*)d_in[3];
    const float* Wk  = (const float*)d_in[4];
    const float* bk  = (const float*)d_in[5];
    const float* Wv  = (const float*)d_in[6];
    const float* bv  = (const float*)d_in[7];
    const float* nqw = (const float*)d_in[8];
    const float* nkw = (const float*)d_in[9];
    const float* hks = (const float*)d_in[10];
    const float* Wo  = (const float*)d_in[11];
    const float* bo  = (const float*)d_in[12];
    const int*   ocl = (const int*)d_in[13];   // int32 view works for int32/int64 LE
    float* out = (float*)d_out;

    float *qp, *kp, *vp, *ap;
    cudaGetSymbolAddress((void**)&qp, g_q);
    cudaGetSymbolAddress((void**)&kp, g_k);
    cudaGetSymbolAddress((void**)&vp, g_v);
    cudaGetSymbolAddress((void**)&ap, g_attn);

    dim3 gg(DIMV / 128, MROWS / 128);
    sgemm_bias_kernel<<<gg, 256>>>(hs, Wq, bq, qp, MROWS, DIMV, DIMV);
    sgemm_bias_kernel<<<gg, 256>>>(hs, Wk, bk, kp, MROWS, DIMV, DIMV);
    sgemm_bias_kernel<<<gg, 256>>>(hs, Wv, bv, vp, MROWS, DIMV, DIMV);

    normrope_kernel<<<MROWS, 256>>>(qp, kp, rot, nqw, nkw, hks, ocl);

    cudaFuncSetAttribute(flashattn_kernel,
                         cudaFuncAttributeMaxDynamicSharedMemorySize, (int)ATT_SMEM);
    flashattn_kernel<<<dim3(SEQ / BQ, BATCH * HEADS), 256, ATT_SMEM>>>(qp, kp, vp, ap);

    sgemm_bias_kernel<<<gg, 256>>>(ap, Wo, bo, out, MROWS, DIMV, DIMV);
}